// round 5
// baseline (speedup 1.0000x reference)
#include <cuda_runtime.h>
#include <math.h>

#define B_  2
#define N_  8
#define K_  8
#define C_  256
#define HW_ 9216
#define BN_ (B_*N_)

// ---------------- scratch (__device__ globals: no allocation allowed) -------
__device__ float d_wsum[BN_*C_];     // sum(value*mask) over HW
__device__ float d_vsum[BN_*C_];     // sum(value) over HW
__device__ float d_msum[BN_];        // sum(mask) over HW
__device__ float d_maxes[2];         // global age max, usage max
__device__ float d_validf[BN_*K_];   // decoded `valid` (dtype-sniffed)
__device__ float d_pnew[BN_*K_*C_];  // proto_new
__device__ float d_bnn [BN_*K_*C_];  // l2norm(proto_new)
__device__ float d_vldn[BN_*K_];     // valid_new as float
__device__ int   d_anyv[BN_];        // any(valid_new)

__device__ __forceinline__ float warpSum(float v) {
    #pragma unroll
    for (int o = 16; o; o >>= 1) v += __shfl_xor_sync(0xffffffffu, v, o);
    return v;
}
__device__ __forceinline__ float warpMax(float v) {
    #pragma unroll
    for (int o = 16; o; o >>= 1) v = fmaxf(v, __shfl_xor_sync(0xffffffffu, v, o));
    return v;
}

// ---------------- kernel 0: decode `valid` with dtype sniff -----------------
// Reads only the first 128 bytes for the sniff (present under every layout).
// int32 0/1 data  -> words all in {0,1}
// float32 0.0/1.0 -> words all in {0, 0x3f800000}
// uint8 bool      -> neither (prob ~8^-32 for random 0/1 bytes)
__global__ void k_valid(const void* __restrict__ valid) {
    __shared__ int s_mode;   // 0=uint8, 1=int32, 2=float32
    const unsigned int* w = (const unsigned int*)valid;
    if (threadIdx.x == 0) {
        int isInt = 1, isFlt = 1;
        for (int i = 0; i < 32; i++) {
            unsigned int x = w[i];
            isInt &= (x <= 1u);
            isFlt &= (x == 0u || x == 0x3f800000u);
        }
        s_mode = isInt ? 1 : (isFlt ? 2 : 0);
    }
    __syncthreads();
    int t = threadIdx.x;     // 128 threads, BN_*K_ = 128
    int v;
    if (s_mode == 1)      v = ((const int*)valid)[t] != 0;
    else if (s_mode == 2) v = ((const float*)valid)[t] != 0.0f;
    else                  v = ((const unsigned char*)valid)[t] != 0;
    d_validf[t] = v ? 1.0f : 0.0f;
}

// ---------------- kernel 1: global max of age / usage (128 elems) ----------
__global__ void k_maxes(const float* __restrict__ age, const float* __restrict__ usage) {
    int t = threadIdx.x;           // 128 threads
    float a = age[t], u = usage[t];
    a = warpMax(a); u = warpMax(u);
    __shared__ float sa[4], su[4];
    if ((t & 31) == 0) { sa[t >> 5] = a; su[t >> 5] = u; }
    __syncthreads();
    if (t == 0) {
        float A = sa[0], U = su[0];
        #pragma unroll
        for (int i = 1; i < 4; i++) { A = fmaxf(A, sa[i]); U = fmaxf(U, su[i]); }
        d_maxes[0] = A; d_maxes[1] = U;
    }
}

// ---------------- kernel 2: sum(mask) per (b,n) ----------------------------
__global__ void k_msum(const float* __restrict__ mask) {
    int bn = blockIdx.x, t = threadIdx.x;                 // 256 threads
    const float4* m4 = (const float4*)(mask + (size_t)bn * HW_);
    float s = 0.f;
    #pragma unroll
    for (int i = 0; i < 9; i++) {                          // 9216/4/256 = 9
        float4 m = m4[i * 256 + t];
        s += m.x + m.y + m.z + m.w;
    }
    s = warpSum(s);
    __shared__ float sb[8];
    if ((t & 31) == 0) sb[t >> 5] = s;
    __syncthreads();
    if (t == 0) {
        float r = 0.f;
        #pragma unroll
        for (int i = 0; i < 8; i++) r += sb[i];
        d_msum[bn] = r;
    }
}

// ---------------- kernel 3: masked pooling sums over HW --------------------
// grid (C, N, B), 256 threads. Reads full value once (151 MB).
__global__ void __launch_bounds__(256) k_candsum(const float* __restrict__ value,
                                                 const float* __restrict__ mask) {
    int c  = blockIdx.x;
    int bn = blockIdx.z * N_ + blockIdx.y;
    int t  = threadIdx.x;
    const float4* v4 = (const float4*)(value + ((size_t)bn * C_ + c) * HW_);
    const float4* m4 = (const float4*)(mask + (size_t)bn * HW_);
    float ws = 0.f, vs = 0.f;
    #pragma unroll
    for (int i = 0; i < 9; i++) {
        float4 v = v4[i * 256 + t];
        float4 m = m4[i * 256 + t];
        ws += v.x * m.x + v.y * m.y + v.z * m.z + v.w * m.w;
        vs += v.x + v.y + v.z + v.w;
    }
    ws = warpSum(ws); vs = warpSum(vs);
    __shared__ float sw[8], sv[8];
    if ((t & 31) == 0) { sw[t >> 5] = ws; sv[t >> 5] = vs; }
    __syncthreads();
    if (t == 0) {
        float a = 0.f, b = 0.f;
        #pragma unroll
        for (int i = 0; i < 8; i++) { a += sw[i]; b += sv[i]; }
        d_wsum[bn * C_ + c] = a;
        d_vsum[bn * C_ + c] = b;
    }
}

// ---------------- kernel 4: policy + bank update ---------------------------
// One block per (b,n), 256 threads (8 warps, warp k handles sim for slot k).
__global__ void __launch_bounds__(256) k_policy(const float* __restrict__ proto,
                                                const float* __restrict__ age,
                                                const float* __restrict__ usage,
                                                const float* __restrict__ conf) {
    int bn = blockIdx.x, t = threadIdx.x;
    __shared__ float s_cand[C_], s_sim[K_], s_red[8];
    __shared__ int s_upd, s_mode;

    // candidate prototype (raw), then l2-normalize
    float msum = d_msum[bn];
    float cc = (msum <= 1e-5f)
             ? d_vsum[bn * C_ + t] * (1.0f / (float)HW_)
             : d_wsum[bn * C_ + t] / fmaxf(msum, 1e-6f);
    float ss = warpSum(cc * cc);
    if ((t & 31) == 0) s_red[t >> 5] = ss;
    __syncthreads();
    float tot = 0.f;
    #pragma unroll
    for (int i = 0; i < 8; i++) tot += s_red[i];
    float cn = cc / fmaxf(sqrtf(tot), 1e-12f);
    s_cand[t] = cn;
    __syncthreads();

    // sim[k] = dot(cand_n, l2norm(proto_k)), -1 if invalid (warp k)
    int w = t >> 5, l = t & 31;
    const float* pbase = proto + (size_t)bn * K_ * C_;
    {
        float ps = 0.f, pd = 0.f;
        #pragma unroll
        for (int i = 0; i < 8; i++) {
            float p = pbase[w * C_ + i * 32 + l];
            ps += p * p;
            pd += p * s_cand[i * 32 + l];
        }
        ps = warpSum(ps); pd = warpSum(pd);
        if (l == 0) {
            float sim = pd / fmaxf(sqrtf(ps), 1e-12f);
            s_sim[w] = (d_validf[bn * K_ + w] > 0.5f) ? sim : -1.0f;
        }
    }
    __syncthreads();

    if (t == 0) {
        bool v[K_]; bool anyv = false, anyi = false;
        #pragma unroll
        for (int k = 0; k < K_; k++) {
            v[k] = (d_validf[bn * K_ + k] > 0.5f);
            anyv |= v[k]; anyi |= !v[k];
        }
        float best = -1e30f; int tgt = 0;
        #pragma unroll
        for (int k = 0; k < K_; k++) if (s_sim[k] > best) { best = s_sim[k]; tgt = k; }
        int target = anyv ? tgt : 0;
        float msim = anyv ? s_sim[target] : -1.0f;
        // A_KEEP=0, A_REFINE=1, A_REPLACE=2, A_SPAWN=3
        int action = (!anyv) ? 3 : ((msim >= 0.8f) ? 1 : ((msim >= 0.3f) ? 0 : 3));
        float am = fmaxf(d_maxes[0], 1.0f), um = fmaxf(d_maxes[1], 1.0f);
        float bs = -1e30f; int vic = 0;
        #pragma unroll
        for (int k = 0; k < K_; k++) {
            float sc = age[bn * K_ + k] / am
                     + (1.0f - usage[bn * K_ + k] / um)
                     + (1.0f - conf[bn * K_ + k]);
            if (sc > bs) { bs = sc; vic = k; }
        }
        int fe = 0;
        for (int k = 0; k < K_; k++) { if (!v[k]) { fe = k; break; } }
        int spawn = anyi ? fe : vic;
        int upd = (action == 1) ? target : spawn;
        int mode = (action == 1) ? 1 : ((action == 3) ? 2 : 0);  // 1=refine, 2=spawn
        s_upd = upd; s_mode = mode;
        d_anyv[bn] = (anyv || mode == 2) ? 1 : 0;
    }
    __syncthreads();
    int upd = s_upd, mode = s_mode;

    // proto_new + bank_nn + valid_new
    for (int k = 0; k < K_; k++) {
        float p = pbase[k * C_ + t];
        float pn = p;
        if (k == upd) {
            if (mode == 1)      pn = 0.7f * p + 0.3f * s_cand[t];  // (1-ALPHA)p + ALPHA*cand
            else if (mode == 2) pn = s_cand[t];
        }
        float q = warpSum(pn * pn);
        __syncthreads();                     // protect s_red reuse
        if ((t & 31) == 0) s_red[t >> 5] = q;
        __syncthreads();
        float nt = 0.f;
        #pragma unroll
        for (int i = 0; i < 8; i++) nt += s_red[i];
        float inv = 1.0f / fmaxf(sqrtf(nt), 1e-12f);
        float pw = pn;
        if (k == upd && mode == 1) pw = pn * inv;   // refine slot stores the normalized vector
        size_t o = (size_t)bn * K_ * C_ + k * C_ + t;
        d_pnew[o] = pw;
        d_bnn[o]  = pn * inv;
        if (t == 0) {
            bool vk = (d_validf[bn * K_ + k] > 0.5f);
            d_vldn[bn * K_ + k] = (vk || (mode == 2 && k == upd)) ? 1.0f : 0.0f;
        }
    }
}

// ---------------- kernel 5: readout + output blend -------------------------
// grid (HW/512, N, B); 256 threads, each handles 2 pixels (float2).
__global__ void __launch_bounds__(256) k_readout(const float* __restrict__ value,
                                                 const float* __restrict__ frame,
                                                 const float* __restrict__ pgate,
                                                 const float* __restrict__ fgate,
                                                 float* __restrict__ out) {
    int tile = blockIdx.x, n = blockIdx.y, b = blockIdx.z;
    int bn = b * N_ + n;
    int t = threadIdx.x;
    __shared__ float s_bnn[K_ * C_], s_pn[K_ * C_], s_vld[K_];
    __shared__ int s_any;
    const size_t off = (size_t)bn * K_ * C_;
    #pragma unroll
    for (int i = 0; i < 8; i++) {
        int j = i * 256 + t;
        s_bnn[j] = d_bnn[off + j];
        s_pn[j]  = d_pnew[off + j];
    }
    if (t < K_) s_vld[t] = d_vldn[bn * K_ + t];
    if (t == 0) s_any = d_anyv[bn];
    __syncthreads();

    int pix = tile * 512 + t * 2;
    const float* vb = value + (size_t)bn * C_ * HW_ + pix;

    float ns0 = 0.f, ns1 = 0.f;
    float r0[K_], r1[K_];
    #pragma unroll
    for (int k = 0; k < K_; k++) { r0[k] = 0.f; r1[k] = 0.f; }

    #pragma unroll 4
    for (int c = 0; c < C_; c++) {
        float2 v = *(const float2*)(vb + (size_t)c * HW_);
        ns0 += v.x * v.x; ns1 += v.y * v.y;
        #pragma unroll
        for (int k = 0; k < K_; k++) {
            float wv = s_bnn[k * C_ + c];
            r0[k] += wv * v.x;
            r1[k] += wv * v.y;
        }
    }
    float i0 = 1.0f / fmaxf(sqrtf(ns0), 1e-12f);
    float i1 = 1.0f / fmaxf(sqrtf(ns1), 1e-12f);

    float a0[K_], a1[K_];
    if (!s_any) {
        #pragma unroll
        for (int k = 0; k < K_; k++) { a0[k] = 0.f; a1[k] = 0.f; }
    } else {
        float m0 = -1e30f, m1 = -1e30f;
        #pragma unroll
        for (int k = 0; k < K_; k++) {
            if (s_vld[k] > 0.5f) {
                m0 = fmaxf(m0, r0[k] * i0);
                m1 = fmaxf(m1, r1[k] * i1);
            }
        }
        float t0 = 0.f, t1 = 0.f;
        #pragma unroll
        for (int k = 0; k < K_; k++) {
            float e0 = (s_vld[k] > 0.5f) ? __expf(r0[k] * i0 - m0) : 0.f;
            float e1 = (s_vld[k] > 0.5f) ? __expf(r1[k] * i1 - m1) : 0.f;
            a0[k] = e0; a1[k] = e1;
            t0 += e0; t1 += e1;
        }
        float z0 = 1.0f / t0, z1 = 1.0f / t1;
        #pragma unroll
        for (int k = 0; k < K_; k++) { a0[k] *= z0; a1[k] *= z1; }
    }

    float pg = *pgate, fg = *fgate;
    const float* fb = frame + (size_t)b * C_ * HW_ + pix;
    float* ob = out + (size_t)bn * C_ * HW_ + pix;
    #pragma unroll 4
    for (int c = 0; c < C_; c++) {
        float2 v = *(const float2*)(vb + (size_t)c * HW_);
        float2 f = *(const float2*)(fb + (size_t)c * HW_);
        float p0 = 0.f, p1 = 0.f;
        #pragma unroll
        for (int k = 0; k < K_; k++) {
            float pw = s_pn[k * C_ + c];
            p0 += a0[k] * pw;
            p1 += a1[k] * pw;
        }
        float2 o;
        o.x = v.x + pg * p0 + fg * f.x;
        o.y = v.y + pg * p1 + fg * f.y;
        *(float2*)(ob + (size_t)c * HW_) = o;
    }
}

// ---------------- launch ----------------------------------------------------
extern "C" void kernel_launch(void* const* d_in, const int* in_sizes, int n_in,
                              void* d_out, int out_size) {
    const float* value = (const float*)d_in[0];
    const float* frame = (const float*)d_in[1];
    const float* mask  = (const float*)d_in[2];
    const float* proto = (const float*)d_in[3];
    const float* age   = (const float*)d_in[4];
    const float* usage = (const float*)d_in[5];
    const float* conf  = (const float*)d_in[6];
    // d_in[7..10] = W1, b1, W2, b2: dead code in the reference (logits unused)
    const float* pgate = (const float*)d_in[11];
    const float* fgate = (const float*)d_in[12];
    const void*  valid = (const void*)d_in[13];
    float* out = (float*)d_out;

    k_valid<<<1, 128>>>(valid);
    k_maxes<<<1, 128>>>(age, usage);
    k_msum<<<BN_, 256>>>(mask);
    dim3 gc(C_, N_, B_);
    k_candsum<<<gc, 256>>>(value, mask);
    k_policy<<<BN_, 256>>>(proto, age, usage, conf);
    dim3 gr(HW_ / 512, N_, B_);
    k_readout<<<gr, 256>>>(value, frame, pgate, fgate, out);
}